// round 1
// baseline (speedup 1.0000x reference)
#include <cuda_runtime.h>
#include <cstdint>

// ---------------- problem constants ----------------
#define BB   64
#define TT   256
#define MROWS (BB*TT)          // 16384
#define DIN  5881
#define DMODEL 64
#define DINNER 128
#define DSTATE 16
#define DTRANK 4
#define NDBL  (DTRANK + 2*DSTATE)   // 36
#define LINDIM 128
#define DIMOUT 256

// ---------------- scratch (static device globals — allowed) ----------------
__device__ float g_z    [MROWS * DMODEL];
__device__ float g_xz   [MROWS * 2 * DINNER];
__device__ float g_xconv[MROWS * DINNER];
__device__ float g_dbl  [MROWS * NDBL];
__device__ float g_dt   [MROWS * DINNER];
__device__ float g_ybar [BB * DINNER];

// ---------------- tf32 GEMM: C[M,N] = A[M,K] @ B[N,K]^T (+bias) ----------------
#define BM 128
#define BN 64
#define BK 32
#define KPAD 36   // BK + 4 -> bank-conflict-free fragment reads

__device__ __forceinline__ unsigned f2tf(float x) {
    unsigned r;
    asm("cvt.rna.tf32.f32 %0, %1;" : "=r"(r) : "f"(x));
    return r;
}

extern __shared__ float smem_dyn[];

__global__ void __launch_bounds__(256, 1) gemm_tf32_kernel(
    const float* __restrict__ A, const float* __restrict__ Bw,
    const float* __restrict__ bias, float* __restrict__ C,
    int M, int N, int K)
{
    float* As = smem_dyn;                 // [2][BM][KPAD]
    float* Bs = smem_dyn + 2 * BM * KPAD; // [2][BN][KPAD]

    const int tid  = threadIdx.x;
    const int lane = tid & 31;
    const int warp = tid >> 5;
    const int wm   = warp & 3;     // 4 warps along M
    const int wn   = warp >> 2;    // 2 warps along N
    const int bm   = blockIdx.x;
    const int bn   = blockIdx.y;

    const int lcol = tid & 31;     // k within tile
    const int lrow = tid >> 5;     // 0..7

    float areg[16];
    float breg[8];

    const int nkt = (K + BK - 1) / BK;

    auto LOAD = [&](int kt) {
        const int k0 = kt * BK + lcol;
        const bool kin = (k0 < K);
        const float* ap = A + (size_t)(bm * BM + lrow) * K + k0;
#pragma unroll
        for (int i = 0; i < 16; i++)
            areg[i] = kin ? ap[(size_t)(i * 8) * K] : 0.f;
#pragma unroll
        for (int i = 0; i < 8; i++) {
            int gn = bn * BN + lrow + i * 8;
            breg[i] = (kin && gn < N) ? Bw[(size_t)gn * K + k0] : 0.f;
        }
    };
    auto STS = [&](int buf) {
        float* as = As + buf * BM * KPAD;
        float* bs = Bs + buf * BN * KPAD;
#pragma unroll
        for (int i = 0; i < 16; i++)
            as[(lrow + i * 8) * KPAD + lcol] = __uint_as_float(f2tf(areg[i]));
#pragma unroll
        for (int i = 0; i < 8; i++)
            bs[(lrow + i * 8) * KPAD + lcol] = __uint_as_float(f2tf(breg[i]));
    };

    float acc[2][4][4];
#pragma unroll
    for (int a = 0; a < 2; a++)
#pragma unroll
        for (int b = 0; b < 4; b++)
#pragma unroll
            for (int c = 0; c < 4; c++) acc[a][b][c] = 0.f;

    LOAD(0);
    STS(0);
    __syncthreads();

    for (int kt = 0; kt < nkt; kt++) {
        const int buf = kt & 1;
        if (kt + 1 < nkt) LOAD(kt + 1);

        const float* as = As + buf * BM * KPAD + (wm * 32) * KPAD;
        const float* bs = Bs + buf * BN * KPAD + (wn * 32) * KPAD;

        const int ar = lane >> 2;
        const int ac = lane & 3;
#pragma unroll
        for (int kk = 0; kk < 4; kk++) {
            const int k0 = kk * 8;
            unsigned a[2][4], b[4][2];
#pragma unroll
            for (int mt = 0; mt < 2; mt++) {
                const float* p = as + (mt * 16 + ar) * KPAD + k0 + ac;
                a[mt][0] = __float_as_uint(p[0]);
                a[mt][1] = __float_as_uint(p[8 * KPAD]);
                a[mt][2] = __float_as_uint(p[4]);
                a[mt][3] = __float_as_uint(p[8 * KPAD + 4]);
            }
#pragma unroll
            for (int nt = 0; nt < 4; nt++) {
                const float* p = bs + (nt * 8 + ar) * KPAD + k0 + ac;
                b[nt][0] = __float_as_uint(p[0]);
                b[nt][1] = __float_as_uint(p[4]);
            }
#pragma unroll
            for (int mt = 0; mt < 2; mt++)
#pragma unroll
                for (int nt = 0; nt < 4; nt++)
                    asm volatile(
                        "mma.sync.aligned.m16n8k8.row.col.f32.tf32.tf32.f32 "
                        "{%0,%1,%2,%3}, {%4,%5,%6,%7}, {%8,%9}, {%0,%1,%2,%3};\n"
                        : "+f"(acc[mt][nt][0]), "+f"(acc[mt][nt][1]),
                          "+f"(acc[mt][nt][2]), "+f"(acc[mt][nt][3])
                        : "r"(a[mt][0]), "r"(a[mt][1]), "r"(a[mt][2]), "r"(a[mt][3]),
                          "r"(b[nt][0]), "r"(b[nt][1]));
        }
        if (kt + 1 < nkt) STS(buf ^ 1);
        __syncthreads();
    }

    // epilogue
    const int row0 = bm * BM + wm * 32 + (lane >> 2);
    const int col0 = bn * BN + wn * 32 + (lane & 3) * 2;
#pragma unroll
    for (int mt = 0; mt < 2; mt++) {
#pragma unroll
        for (int nt = 0; nt < 4; nt++) {
            const int c0 = col0 + nt * 8;
            const int r  = row0 + mt * 16;
            if (c0 < N) {   // N is even in all uses, so c0<N -> c0+1<N
                const float b0v = bias ? bias[c0]     : 0.f;
                const float b1v = bias ? bias[c0 + 1] : 0.f;
                C[(size_t)r * N + c0]           = acc[mt][nt][0] + b0v;
                C[(size_t)r * N + c0 + 1]       = acc[mt][nt][1] + b1v;
                C[(size_t)(r + 8) * N + c0]     = acc[mt][nt][2] + b0v;
                C[(size_t)(r + 8) * N + c0 + 1] = acc[mt][nt][3] + b1v;
            }
        }
    }
}

// ---------------- causal depthwise conv (kernel 4) + bias + SiLU ----------------
__global__ void conv_silu_kernel(const float* __restrict__ xz,
                                 const float* __restrict__ cw,
                                 const float* __restrict__ cb,
                                 float* __restrict__ xconv)
{
    const int gid = blockIdx.x * blockDim.x + threadIdx.x;
    if (gid >= MROWS * DINNER) return;
    const int d = gid & (DINNER - 1);
    const int t = (gid >> 7) & (TT - 1);

    const float w0 = cw[d * 4 + 0], w1 = cw[d * 4 + 1];
    const float w2 = cw[d * 4 + 2], w3 = cw[d * 4 + 3];

    const float* xp = xz + (size_t)(gid >> 7) * (2 * DINNER) + d;  // x part (cols 0..127)
    float acc = cb[d] + xp[0] * w3;
    if (t >= 1) acc += xp[-(2 * DINNER)]     * w2;
    if (t >= 2) acc += xp[-(4 * DINNER)]     * w1;
    if (t >= 3) acc += xp[-(6 * DINNER)]     * w0;

    xconv[gid] = acc / (1.f + __expf(-acc));   // silu
}

// ---------------- dt = softplus(dbl[:, :4] @ W_dt^T + b_dt) ----------------
__global__ void dt_kernel(const float* __restrict__ dbl,
                          const float* __restrict__ Wdt,
                          const float* __restrict__ bdt,
                          float* __restrict__ dtb)
{
    const int gid = blockIdx.x * blockDim.x + threadIdx.x;
    if (gid >= MROWS * DINNER) return;
    const int d   = gid & (DINNER - 1);
    const int row = gid >> 7;
    const float* xr = dbl + (size_t)row * NDBL;
    float v = bdt[d];
#pragma unroll
    for (int r = 0; r < 4; r++) v += xr[r] * Wdt[d * 4 + r];
    dtb[gid] = (v > 20.f) ? v : log1pf(__expf(v));
}

// ---------------- selective scan + gate + D-skip + T-mean ----------------
__device__ __forceinline__ float ex2(float x) {
    float r;
    asm("ex2.approx.ftz.f32 %0, %1;" : "=f"(r) : "f"(x));
    return r;
}

__global__ void __launch_bounds__(128, 1) scan_kernel(
    const float* __restrict__ dbl, const float* __restrict__ dtb,
    const float* __restrict__ xconv, const float* __restrict__ xz,
    const float* __restrict__ A_log, const float* __restrict__ D_skip,
    float* __restrict__ ybar)
{
    const int b = blockIdx.x;
    const int d = threadIdx.x;   // 128

    __shared__ float sB[8][DSTATE];
    __shared__ float sC[8][DSTATE];

    float a2[DSTATE];
#pragma unroll
    for (int n = 0; n < DSTATE; n++)
        a2[n] = -__expf(A_log[d * DSTATE + n]) * 1.4426950408889634f;

    const float dsk = D_skip[d];
    float h[DSTATE];
#pragma unroll
    for (int n = 0; n < DSTATE; n++) h[n] = 0.f;
    float ys = 0.f;

    for (int t0 = 0; t0 < TT; t0 += 8) {
        __syncthreads();
        for (int i = d; i < 8 * 32; i += 128) {
            const int tt = i >> 5, j = i & 31;
            const float v = dbl[(size_t)(b * TT + t0 + tt) * NDBL + DTRANK + j];
            if (j < DSTATE) sB[tt][j] = v;
            else            sC[tt][j - DSTATE] = v;
        }
        __syncthreads();
#pragma unroll
        for (int tt = 0; tt < 8; tt++) {
            const int row = b * TT + t0 + tt;
            const float dtv = dtb[(size_t)row * DINNER + d];
            const float xc  = xconv[(size_t)row * DINNER + d];
            const float g   = xz[(size_t)row * (2 * DINNER) + DINNER + d];
            const float s   = dtv * xc;
            float y = 0.f;
#pragma unroll
            for (int n = 0; n < DSTATE; n++) {
                const float dA = ex2(dtv * a2[n]);
                h[n] = dA * h[n] + s * sB[tt][n];
                y += h[n] * sC[tt][n];
            }
            y += dsk * xc;
            y *= g / (1.f + __expf(-g));   // * silu(gate)
            ys += y;
        }
    }
    ybar[b * DINNER + d] = ys * (1.f / (float)TT);
}

// ---------------- out-proj + heads (uses mean_t(y @ Wout) == mean_t(y) @ Wout) ----------------
__global__ void head_kernel(const float* __restrict__ ybar,
                            const float* __restrict__ Wout,
                            const float* __restrict__ Wfc,  const float* __restrict__ bfc,
                            const float* __restrict__ Wmu,  const float* __restrict__ bmu,
                            const float* __restrict__ Wsig, const float* __restrict__ bsig,
                            float* __restrict__ out)
{
    const int b = blockIdx.x;
    const int tid = threadIdx.x;   // 256
    __shared__ float yb[DINNER], ev[DMODEL], xv[LINDIM];

    if (tid < DINNER) yb[tid] = ybar[b * DINNER + tid];
    __syncthreads();

    if (tid < DMODEL) {
        float a = 0.f;
#pragma unroll 4
        for (int dd = 0; dd < DINNER; dd++) a += yb[dd] * Wout[tid * DINNER + dd];
        ev[tid] = a;
    }
    __syncthreads();

    if (tid < LINDIM) {
        float a = bfc[tid];
#pragma unroll 4
        for (int m = 0; m < DMODEL; m++) a += ev[m] * Wfc[tid * DMODEL + m];
        const float th = tanhf(a);
        const float x = (th > 0.f) ? th : expm1f(th);   // elu
        xv[tid] = x;
        out[b * LINDIM + tid] = x;
    }
    __syncthreads();

    {
        const int o = tid;   // 0..255
        float m = bmu[o], sg = bsig[o];
#pragma unroll 4
        for (int j = 0; j < LINDIM; j++) {
            const float xj = xv[j];
            m  += xj * Wmu[o * LINDIM + j];
            sg += xj * Wsig[o * LINDIM + j];
        }
        out[BB * LINDIM + b * DIMOUT + o] = m;
        const float el = (sg > 0.f) ? sg : expm1f(sg);
        out[BB * LINDIM + BB * DIMOUT + b * DIMOUT + o] = el + 1.f + 1e-14f;
    }
}

// ---------------- launch ----------------
extern "C" void kernel_launch(void* const* d_in, const int* in_sizes, int n_in,
                              void* d_out, int out_size)
{
    const float* input  = (const float*)d_in[0];
    const float* W_enc  = (const float*)d_in[1];
    const float* b_enc  = (const float*)d_in[2];
    const float* W_in   = (const float*)d_in[3];
    const float* conv_w = (const float*)d_in[4];
    const float* conv_b = (const float*)d_in[5];
    const float* W_x    = (const float*)d_in[6];
    const float* W_dt   = (const float*)d_in[7];
    const float* b_dt   = (const float*)d_in[8];
    const float* A_log  = (const float*)d_in[9];
    const float* D_skip = (const float*)d_in[10];
    const float* W_out  = (const float*)d_in[11];
    const float* W_fc   = (const float*)d_in[12];
    const float* b_fc   = (const float*)d_in[13];
    const float* W_mu   = (const float*)d_in[14];
    const float* b_mu   = (const float*)d_in[15];
    const float* W_sig  = (const float*)d_in[16];
    const float* b_sig  = (const float*)d_in[17];
    float* out = (float*)d_out;

    float *z, *xz, *xconv, *dbl, *dtb, *ybar;
    cudaGetSymbolAddress((void**)&z,     g_z);
    cudaGetSymbolAddress((void**)&xz,    g_xz);
    cudaGetSymbolAddress((void**)&xconv, g_xconv);
    cudaGetSymbolAddress((void**)&dbl,   g_dbl);
    cudaGetSymbolAddress((void**)&dtb,   g_dt);
    cudaGetSymbolAddress((void**)&ybar,  g_ybar);

    const int smemBytes = (2 * BM * KPAD + 2 * BN * KPAD) * (int)sizeof(float); // 55296
    cudaFuncSetAttribute(gemm_tf32_kernel,
                         cudaFuncAttributeMaxDynamicSharedMemorySize, smemBytes);

    // 1. encoder: z = input @ W_enc^T + b_enc
    gemm_tf32_kernel<<<dim3(MROWS / BM, 1), 256, smemBytes>>>(
        input, W_enc, b_enc, z, MROWS, DMODEL, DIN);

    // 2. xz = z @ W_in^T
    gemm_tf32_kernel<<<dim3(MROWS / BM, (2 * DINNER) / BN), 256, smemBytes>>>(
        z, W_in, nullptr, xz, MROWS, 2 * DINNER, DMODEL);

    // 3. causal conv + silu
    conv_silu_kernel<<<(MROWS * DINNER) / 256, 256>>>(xz, conv_w, conv_b, xconv);

    // 4. dbl = x_conv @ W_x^T   (N=36, guarded)
    gemm_tf32_kernel<<<dim3(MROWS / BM, 1), 256, smemBytes>>>(
        xconv, W_x, nullptr, dbl, MROWS, NDBL, DINNER);

    // 5. dt = softplus(dbl[:, :4] @ W_dt^T + b_dt)
    dt_kernel<<<(MROWS * DINNER) / 256, 256>>>(dbl, W_dt, b_dt, dtb);

    // 6. selective scan + gate + skip + T-mean
    scan_kernel<<<BB, DINNER>>>(dbl, dtb, xconv, xz, A_log, D_skip, ybar);

    // 7. out-proj + heads -> (x, mu, sigma)
    head_kernel<<<BB, 256>>>(ybar, W_out, W_fc, b_fc, W_mu, b_mu, W_sig, b_sig, out);
}

// round 2
// speedup vs baseline: 1.2618x; 1.2618x over previous
#include <cuda_runtime.h>
#include <cstdint>

// ---------------- problem constants ----------------
#define BB   64
#define TT   256
#define MROWS (BB*TT)          // 16384
#define DIN  5881
#define DMODEL 64
#define DINNER 128
#define DSTATE 16
#define DTRANK 4
#define NDBL  (DTRANK + 2*DSTATE)   // 36
#define LINDIM 128
#define DIMOUT 256

// ---------------- scratch (static device globals — allowed) ----------------
__device__ float g_z    [MROWS * DMODEL];
__device__ float g_xz   [MROWS * 2 * DINNER];
__device__ float g_xconv[MROWS * DINNER];
__device__ float g_dbl  [MROWS * NDBL];
__device__ float g_dt   [MROWS * DINNER];
__device__ float g_ybar [BB * DINNER];

// ================= cp.async helpers =================
__device__ __forceinline__ void cp_async4(void* smem, const void* gmem, int bytes) {
    unsigned s = (unsigned)__cvta_generic_to_shared(smem);
    asm volatile("cp.async.ca.shared.global [%0], [%1], 4, %2;\n"
                 :: "r"(s), "l"(gmem), "r"(bytes));
}
#define CP_COMMIT()  asm volatile("cp.async.commit_group;\n" ::: "memory")
#define CP_WAIT(n)   asm volatile("cp.async.wait_group %0;\n" :: "n"(n) : "memory")

// ================= encoder GEMM: split-K, cp.async 3-stage, tf32 MMA =================
// C[M,64] += A[M,K] @ B[64,K]^T     (C pre-initialized with bias; atomicAdd epilogue)
#define EBM 128
#define EBN 64
#define EBK 32
#define ESTAGES 3
#define EKPAD 36                         // 36 floats/row -> conflict-free frag reads
#define ESTAGE_FLTS ((EBM + EBN) * EKPAD)   // 6912 floats per stage
#define NSPLIT 4
#define NKT_TOTAL ((DIN + EBK - 1) / EBK)   // 184
#define KT_PER_SPLIT (NKT_TOTAL / NSPLIT)   // 46 (exact)

extern __shared__ float smem_dyn[];

__global__ void __launch_bounds__(256, 2) enc_gemm_kernel(
    const float* __restrict__ A, const float* __restrict__ Bw,
    float* __restrict__ C)
{
    const int tid  = threadIdx.x;
    const int lane = tid & 31;
    const int w    = tid >> 5;          // warp 0..7
    const int wm   = w & 3;             // 4 warps along M
    const int wn   = w >> 2;            // 2 warps along N
    const int bm   = blockIdx.x;
    const int ktb  = blockIdx.z * KT_PER_SPLIT;

    const float* Arow = A + (size_t)(bm * EBM) * DIN;

    // issue one k-tile stage into buffer `buf`
    auto ISSUE = [&](int kt, int buf) {
        float* sb = smem_dyn + buf * ESTAGE_FLTS;
        const int kg = kt * EBK + lane;
        const int bytes = (kg < DIN) ? 4 : 0;
        // A: rows 8i + w, i = 0..15
#pragma unroll
        for (int i = 0; i < 16; i++) {
            const int row = 8 * i + w;
            cp_async4(sb + row * EKPAD + lane, Arow + (size_t)row * DIN + kg, bytes);
        }
        // B: rows 8i + w, i = 0..7
        float* sbB = sb + EBM * EKPAD;
#pragma unroll
        for (int i = 0; i < 8; i++) {
            const int row = 8 * i + w;
            cp_async4(sbB + row * EKPAD + lane, Bw + (size_t)row * DIN + kg, bytes);
        }
    };

    float acc[2][4][4];
#pragma unroll
    for (int a = 0; a < 2; a++)
#pragma unroll
        for (int b = 0; b < 4; b++)
#pragma unroll
            for (int c = 0; c < 4; c++) acc[a][b][c] = 0.f;

    // prologue: fill stages 0,1
    ISSUE(ktb + 0, 0); CP_COMMIT();
    ISSUE(ktb + 1, 1); CP_COMMIT();

    const int ar = lane >> 2;
    const int ac = lane & 3;

    for (int i = 0; i < KT_PER_SPLIT; i++) {
        CP_WAIT(1);
        __syncthreads();

        const int buf = i % ESTAGES;
        const float* as = smem_dyn + buf * ESTAGE_FLTS + (wm * 32) * EKPAD;
        const float* bs = smem_dyn + buf * ESTAGE_FLTS + EBM * EKPAD + (wn * 32) * EKPAD;

#pragma unroll
        for (int kk = 0; kk < 4; kk++) {
            const int k0 = kk * 8;
            unsigned a[2][4], b[4][2];
#pragma unroll
            for (int mt = 0; mt < 2; mt++) {
                const float* p = as + (mt * 16 + ar) * EKPAD + k0 + ac;
                a[mt][0] = __float_as_uint(p[0]);
                a[mt][1] = __float_as_uint(p[8 * EKPAD]);
                a[mt][2] = __float_as_uint(p[4]);
                a[mt][3] = __float_as_uint(p[8 * EKPAD + 4]);
            }
#pragma unroll
            for (int nt = 0; nt < 4; nt++) {
                const float* p = bs + (nt * 8 + ar) * EKPAD + k0 + ac;
                b[nt][0] = __float_as_uint(p[0]);
                b[nt][1] = __float_as_uint(p[4]);
            }
#pragma unroll
            for (int mt = 0; mt < 2; mt++)
#pragma unroll
                for (int nt = 0; nt < 4; nt++)
                    asm volatile(
                        "mma.sync.aligned.m16n8k8.row.col.f32.tf32.tf32.f32 "
                        "{%0,%1,%2,%3}, {%4,%5,%6,%7}, {%8,%9}, {%0,%1,%2,%3};\n"
                        : "+f"(acc[mt][nt][0]), "+f"(acc[mt][nt][1]),
                          "+f"(acc[mt][nt][2]), "+f"(acc[mt][nt][3])
                        : "r"(a[mt][0]), "r"(a[mt][1]), "r"(a[mt][2]), "r"(a[mt][3]),
                          "r"(b[nt][0]), "r"(b[nt][1]));
        }

        const int nkt = i + ESTAGES - 1;           // next stage to issue
        if (nkt < KT_PER_SPLIT) ISSUE(ktb + nkt, nkt % ESTAGES);
        CP_COMMIT();
    }

    // epilogue: atomic accumulate into pre-biased C
    const int row0 = bm * EBM + wm * 32 + (lane >> 2);
    const int col0 = wn * 32 + (lane & 3) * 2;
#pragma unroll
    for (int mt = 0; mt < 2; mt++) {
#pragma unroll
        for (int nt = 0; nt < 4; nt++) {
            const int c0 = col0 + nt * 8;
            const int r  = row0 + mt * 16;
            atomicAdd(&C[(size_t)r * EBN + c0],           acc[mt][nt][0]);
            atomicAdd(&C[(size_t)r * EBN + c0 + 1],       acc[mt][nt][1]);
            atomicAdd(&C[(size_t)(r + 8) * EBN + c0],     acc[mt][nt][2]);
            atomicAdd(&C[(size_t)(r + 8) * EBN + c0 + 1], acc[mt][nt][3]);
        }
    }
}

// bias pre-fill for the atomic epilogue
__global__ void z_init_kernel(const float* __restrict__ b_enc, float* __restrict__ z)
{
    const int idx = blockIdx.x * blockDim.x + threadIdx.x;
    if (idx < MROWS * DMODEL) z[idx] = b_enc[idx & (DMODEL - 1)];
}

// ================= generic tf32 GEMM (small GEMMs: xz, dbl) =================
#define BM 128
#define BN 64
#define BK 32
#define KPAD 36

__device__ __forceinline__ unsigned f2tf(float x) {
    unsigned r;
    asm("cvt.rna.tf32.f32 %0, %1;" : "=r"(r) : "f"(x));
    return r;
}

__global__ void __launch_bounds__(256, 1) gemm_tf32_kernel(
    const float* __restrict__ A, const float* __restrict__ Bw,
    const float* __restrict__ bias, float* __restrict__ C,
    int M, int N, int K)
{
    float* As = smem_dyn;
    float* Bs = smem_dyn + 2 * BM * KPAD;

    const int tid  = threadIdx.x;
    const int lane = tid & 31;
    const int warp = tid >> 5;
    const int wm   = warp & 3;
    const int wn   = warp >> 2;
    const int bm   = blockIdx.x;
    const int bn   = blockIdx.y;

    const int lcol = tid & 31;
    const int lrow = tid >> 5;

    float areg[16];
    float breg[8];

    const int nkt = (K + BK - 1) / BK;

    auto LOAD = [&](int kt) {
        const int k0 = kt * BK + lcol;
        const bool kin = (k0 < K);
        const float* ap = A + (size_t)(bm * BM + lrow) * K + k0;
#pragma unroll
        for (int i = 0; i < 16; i++)
            areg[i] = kin ? ap[(size_t)(i * 8) * K] : 0.f;
#pragma unroll
        for (int i = 0; i < 8; i++) {
            int gn = bn * BN + lrow + i * 8;
            breg[i] = (kin && gn < N) ? Bw[(size_t)gn * K + k0] : 0.f;
        }
    };
    auto STS = [&](int buf) {
        float* as = As + buf * BM * KPAD;
        float* bs = Bs + buf * BN * KPAD;
#pragma unroll
        for (int i = 0; i < 16; i++)
            as[(lrow + i * 8) * KPAD + lcol] = __uint_as_float(f2tf(areg[i]));
#pragma unroll
        for (int i = 0; i < 8; i++)
            bs[(lrow + i * 8) * KPAD + lcol] = __uint_as_float(f2tf(breg[i]));
    };

    float acc[2][4][4];
#pragma unroll
    for (int a = 0; a < 2; a++)
#pragma unroll
        for (int b = 0; b < 4; b++)
#pragma unroll
            for (int c = 0; c < 4; c++) acc[a][b][c] = 0.f;

    LOAD(0);
    STS(0);
    __syncthreads();

    for (int kt = 0; kt < nkt; kt++) {
        const int buf = kt & 1;
        if (kt + 1 < nkt) LOAD(kt + 1);

        const float* as = As + buf * BM * KPAD + (wm * 32) * KPAD;
        const float* bs = Bs + buf * BN * KPAD + (wn * 32) * KPAD;

        const int ar = lane >> 2;
        const int ac = lane & 3;
#pragma unroll
        for (int kk = 0; kk < 4; kk++) {
            const int k0 = kk * 8;
            unsigned a[2][4], b[4][2];
#pragma unroll
            for (int mt = 0; mt < 2; mt++) {
                const float* p = as + (mt * 16 + ar) * KPAD + k0 + ac;
                a[mt][0] = __float_as_uint(p[0]);
                a[mt][1] = __float_as_uint(p[8 * KPAD]);
                a[mt][2] = __float_as_uint(p[4]);
                a[mt][3] = __float_as_uint(p[8 * KPAD + 4]);
            }
#pragma unroll
            for (int nt = 0; nt < 4; nt++) {
                const float* p = bs + (nt * 8 + ar) * KPAD + k0 + ac;
                b[nt][0] = __float_as_uint(p[0]);
                b[nt][1] = __float_as_uint(p[4]);
            }
#pragma unroll
            for (int mt = 0; mt < 2; mt++)
#pragma unroll
                for (int nt = 0; nt < 4; nt++)
                    asm volatile(
                        "mma.sync.aligned.m16n8k8.row.col.f32.tf32.tf32.f32 "
                        "{%0,%1,%2,%3}, {%4,%5,%6,%7}, {%8,%9}, {%0,%1,%2,%3};\n"
                        : "+f"(acc[mt][nt][0]), "+f"(acc[mt][nt][1]),
                          "+f"(acc[mt][nt][2]), "+f"(acc[mt][nt][3])
                        : "r"(a[mt][0]), "r"(a[mt][1]), "r"(a[mt][2]), "r"(a[mt][3]),
                          "r"(b[nt][0]), "r"(b[nt][1]));
        }
        if (kt + 1 < nkt) STS(buf ^ 1);
        __syncthreads();
    }

    const int row0 = bm * BM + wm * 32 + (lane >> 2);
    const int col0 = bn * BN + wn * 32 + (lane & 3) * 2;
#pragma unroll
    for (int mt = 0; mt < 2; mt++) {
#pragma unroll
        for (int nt = 0; nt < 4; nt++) {
            const int c0 = col0 + nt * 8;
            const int r  = row0 + mt * 16;
            if (c0 < N) {
                const float b0v = bias ? bias[c0]     : 0.f;
                const float b1v = bias ? bias[c0 + 1] : 0.f;
                C[(size_t)r * N + c0]           = acc[mt][nt][0] + b0v;
                C[(size_t)r * N + c0 + 1]       = acc[mt][nt][1] + b1v;
                C[(size_t)(r + 8) * N + c0]     = acc[mt][nt][2] + b0v;
                C[(size_t)(r + 8) * N + c0 + 1] = acc[mt][nt][3] + b1v;
            }
        }
    }
}

// ---------------- causal depthwise conv (kernel 4) + bias + SiLU ----------------
__global__ void conv_silu_kernel(const float* __restrict__ xz,
                                 const float* __restrict__ cw,
                                 const float* __restrict__ cb,
                                 float* __restrict__ xconv)
{
    const int gid = blockIdx.x * blockDim.x + threadIdx.x;
    if (gid >= MROWS * DINNER) return;
    const int d = gid & (DINNER - 1);
    const int t = (gid >> 7) & (TT - 1);

    const float w0 = cw[d * 4 + 0], w1 = cw[d * 4 + 1];
    const float w2 = cw[d * 4 + 2], w3 = cw[d * 4 + 3];

    const float* xp = xz + (size_t)(gid >> 7) * (2 * DINNER) + d;
    float acc = cb[d] + xp[0] * w3;
    if (t >= 1) acc += xp[-(2 * DINNER)] * w2;
    if (t >= 2) acc += xp[-(4 * DINNER)] * w1;
    if (t >= 3) acc += xp[-(6 * DINNER)] * w0;

    xconv[gid] = acc / (1.f + __expf(-acc));
}

// ---------------- dt = softplus(dbl[:, :4] @ W_dt^T + b_dt) ----------------
__global__ void dt_kernel(const float* __restrict__ dbl,
                          const float* __restrict__ Wdt,
                          const float* __restrict__ bdt,
                          float* __restrict__ dtb)
{
    const int gid = blockIdx.x * blockDim.x + threadIdx.x;
    if (gid >= MROWS * DINNER) return;
    const int d   = gid & (DINNER - 1);
    const int row = gid >> 7;
    const float* xr = dbl + (size_t)row * NDBL;
    float v = bdt[d];
#pragma unroll
    for (int r = 0; r < 4; r++) v += xr[r] * Wdt[d * 4 + r];
    dtb[gid] = (v > 20.f) ? v : log1pf(__expf(v));
}

// ---------------- selective scan + gate + D-skip + T-mean ----------------
__device__ __forceinline__ float ex2(float x) {
    float r;
    asm("ex2.approx.ftz.f32 %0, %1;" : "=f"(r) : "f"(x));
    return r;
}

__global__ void __launch_bounds__(128, 1) scan_kernel(
    const float* __restrict__ dbl, const float* __restrict__ dtb,
    const float* __restrict__ xconv, const float* __restrict__ xz,
    const float* __restrict__ A_log, const float* __restrict__ D_skip,
    float* __restrict__ ybar)
{
    const int b = blockIdx.x;
    const int d = threadIdx.x;

    __shared__ float sB[8][DSTATE];
    __shared__ float sC[8][DSTATE];

    float a2[DSTATE];
#pragma unroll
    for (int n = 0; n < DSTATE; n++)
        a2[n] = -__expf(A_log[d * DSTATE + n]) * 1.4426950408889634f;

    const float dsk = D_skip[d];
    float h[DSTATE];
#pragma unroll
    for (int n = 0; n < DSTATE; n++) h[n] = 0.f;
    float ys = 0.f;

    for (int t0 = 0; t0 < TT; t0 += 8) {
        __syncthreads();
        for (int i = d; i < 8 * 32; i += 128) {
            const int tt = i >> 5, j = i & 31;
            const float v = dbl[(size_t)(b * TT + t0 + tt) * NDBL + DTRANK + j];
            if (j < DSTATE) sB[tt][j] = v;
            else            sC[tt][j - DSTATE] = v;
        }
        __syncthreads();
#pragma unroll
        for (int tt = 0; tt < 8; tt++) {
            const int row = b * TT + t0 + tt;
            const float dtv = dtb[(size_t)row * DINNER + d];
            const float xc  = xconv[(size_t)row * DINNER + d];
            const float g   = xz[(size_t)row * (2 * DINNER) + DINNER + d];
            const float s   = dtv * xc;
            float y = 0.f;
#pragma unroll
            for (int n = 0; n < DSTATE; n++) {
                const float dA = ex2(dtv * a2[n]);
                h[n] = dA * h[n] + s * sB[tt][n];
                y += h[n] * sC[tt][n];
            }
            y += dsk * xc;
            y *= g / (1.f + __expf(-g));
            ys += y;
        }
    }
    ybar[b * DINNER + d] = ys * (1.f / (float)TT);
}

// ---------------- out-proj + heads ----------------
__global__ void head_kernel(const float* __restrict__ ybar,
                            const float* __restrict__ Wout,
                            const float* __restrict__ Wfc,  const float* __restrict__ bfc,
                            const float* __restrict__ Wmu,  const float* __restrict__ bmu,
                            const float* __restrict__ Wsig, const float* __restrict__ bsig,
                            float* __restrict__ out)
{
    const int b = blockIdx.x;
    const int tid = threadIdx.x;
    __shared__ float yb[DINNER], ev[DMODEL], xv[LINDIM];

    if (tid < DINNER) yb[tid] = ybar[b * DINNER + tid];
    __syncthreads();

    if (tid < DMODEL) {
        float a = 0.f;
#pragma unroll 4
        for (int dd = 0; dd < DINNER; dd++) a += yb[dd] * Wout[tid * DINNER + dd];
        ev[tid] = a;
    }
    __syncthreads();

    if (tid < LINDIM) {
        float a = bfc[tid];
#pragma unroll 4
        for (int m = 0; m < DMODEL; m++) a += ev[m] * Wfc[tid * DMODEL + m];
        const float th = tanhf(a);
        const float x = (th > 0.f) ? th : expm1f(th);
        xv[tid] = x;
        out[b * LINDIM + tid] = x;
    }
    __syncthreads();

    {
        const int o = tid;
        float m = bmu[o], sg = bsig[o];
#pragma unroll 4
        for (int j = 0; j < LINDIM; j++) {
            const float xj = xv[j];
            m  += xj * Wmu[o * LINDIM + j];
            sg += xj * Wsig[o * LINDIM + j];
        }
        out[BB * LINDIM + b * DIMOUT + o] = m;
        const float el = (sg > 0.f) ? sg : expm1f(sg);
        out[BB * LINDIM + BB * DIMOUT + b * DIMOUT + o] = el + 1.f + 1e-14f;
    }
}

// ---------------- launch ----------------
extern "C" void kernel_launch(void* const* d_in, const int* in_sizes, int n_in,
                              void* d_out, int out_size)
{
    const float* input  = (const float*)d_in[0];
    const float* W_enc  = (const float*)d_in[1];
    const float* b_enc  = (const float*)d_in[2];
    const float* W_in   = (const float*)d_in[3];
    const float* conv_w = (const float*)d_in[4];
    const float* conv_b = (const float*)d_in[5];
    const float* W_x    = (const float*)d_in[6];
    const float* W_dt   = (const float*)d_in[7];
    const float* b_dt   = (const float*)d_in[8];
    const float* A_log  = (const float*)d_in[9];
    const float* D_skip = (const float*)d_in[10];
    const float* W_out  = (const float*)d_in[11];
    const float* W_fc   = (const float*)d_in[12];
    const float* b_fc   = (const float*)d_in[13];
    const float* W_mu   = (const float*)d_in[14];
    const float* b_mu   = (const float*)d_in[15];
    const float* W_sig  = (const float*)d_in[16];
    const float* b_sig  = (const float*)d_in[17];
    float* out = (float*)d_out;

    float *z, *xz, *xconv, *dbl, *dtb, *ybar;
    cudaGetSymbolAddress((void**)&z,     g_z);
    cudaGetSymbolAddress((void**)&xz,    g_xz);
    cudaGetSymbolAddress((void**)&xconv, g_xconv);
    cudaGetSymbolAddress((void**)&dbl,   g_dbl);
    cudaGetSymbolAddress((void**)&dtb,   g_dt);
    cudaGetSymbolAddress((void**)&ybar,  g_ybar);

    const int encSmem = ESTAGES * ESTAGE_FLTS * (int)sizeof(float);   // 82944
    cudaFuncSetAttribute(enc_gemm_kernel,
                         cudaFuncAttributeMaxDynamicSharedMemorySize, encSmem);
    const int smemBytes = (2 * BM * KPAD + 2 * BN * KPAD) * (int)sizeof(float); // 55296
    cudaFuncSetAttribute(gemm_tf32_kernel,
                         cudaFuncAttributeMaxDynamicSharedMemorySize, smemBytes);

    // 1a. z = bias
    z_init_kernel<<<(MROWS * DMODEL) / 256, 256>>>(b_enc, z);
    // 1b. z += input @ W_enc^T   (split-K x4, cp.async pipelined)
    enc_gemm_kernel<<<dim3(MROWS / EBM, 1, NSPLIT), 256, encSmem>>>(input, W_enc, z);

    // 2. xz = z @ W_in^T
    gemm_tf32_kernel<<<dim3(MROWS / BM, (2 * DINNER) / BN), 256, smemBytes>>>(
        z, W_in, nullptr, xz, MROWS, 2 * DINNER, DMODEL);

    // 3. causal conv + silu
    conv_silu_kernel<<<(MROWS * DINNER) / 256, 256>>>(xz, conv_w, conv_b, xconv);

    // 4. dbl = x_conv @ W_x^T
    gemm_tf32_kernel<<<dim3(MROWS / BM, 1), 256, smemBytes>>>(
        xconv, W_x, nullptr, dbl, MROWS, NDBL, DINNER);

    // 5. dt = softplus(dbl[:, :4] @ W_dt^T + b_dt)
    dt_kernel<<<(MROWS * DINNER) / 256, 256>>>(dbl, W_dt, b_dt, dtb);

    // 6. selective scan + gate + skip + T-mean
    scan_kernel<<<BB, DINNER>>>(dbl, dtb, xconv, xz, A_log, D_skip, ybar);

    // 7. out-proj + heads -> (x, mu, sigma)
    head_kernel<<<BB, 256>>>(ybar, W_out, W_fc, b_fc, W_mu, b_mu, W_sig, b_sig, out);
}

// round 3
// speedup vs baseline: 1.2689x; 1.0056x over previous
#include <cuda_runtime.h>
#include <cstdint>

// ---------------- problem constants ----------------
#define BB   64
#define TT   256
#define MROWS (BB*TT)          // 16384
#define DIN  5881
#define DMODEL 64
#define DINNER 128
#define DSTATE 16
#define DTRANK 4
#define NDBL  (DTRANK + 2*DSTATE)   // 36
#define LINDIM 128
#define DIMOUT 256

// ---------------- scratch (static device globals — allowed) ----------------
__device__ float g_z    [MROWS * DMODEL];
__device__ float g_xz   [MROWS * 2 * DINNER];
__device__ float g_xconv[MROWS * DINNER];
__device__ float g_dbl  [MROWS * NDBL];
__device__ float g_dt   [MROWS * DINNER];
__device__ float g_ybar [BB * DINNER];

// ================= cp.async helpers =================
__device__ __forceinline__ void cp_async4(void* smem, const void* gmem, int bytes) {
    unsigned s = (unsigned)__cvta_generic_to_shared(smem);
    asm volatile("cp.async.ca.shared.global [%0], [%1], 4, %2;\n"
                 :: "r"(s), "l"(gmem), "r"(bytes));
}
#define CP_COMMIT()  asm volatile("cp.async.commit_group;\n" ::: "memory")
#define CP_WAIT(n)   asm volatile("cp.async.wait_group %0;\n" :: "n"(n) : "memory")

// ================= encoder GEMM: split-K, cp.async 3-stage, tf32 MMA =================
// C[M,64] += A[M,K] @ B[64,K]^T     (C pre-initialized with bias; atomicAdd epilogue)
#define EBM 128
#define EBN 64
#define EBK 32
#define ESTAGES 3
#define EKPAD 36                         // 36 floats/row -> conflict-free frag reads
#define ESTAGE_FLTS ((EBM + EBN) * EKPAD)   // 6912 floats per stage
#define NSPLIT 4
#define NKT_TOTAL ((DIN + EBK - 1) / EBK)   // 184
#define KT_PER_SPLIT (NKT_TOTAL / NSPLIT)   // 46 (exact)

extern __shared__ float smem_dyn[];

__global__ void __launch_bounds__(256, 2) enc_gemm_kernel(
    const float* __restrict__ A, const float* __restrict__ Bw,
    float* __restrict__ C)
{
    const int tid  = threadIdx.x;
    const int lane = tid & 31;
    const int w    = tid >> 5;          // warp 0..7
    const int wm   = w & 3;             // 4 warps along M
    const int wn   = w >> 2;            // 2 warps along N
    const int bm   = blockIdx.x;
    const int ktb  = blockIdx.z * KT_PER_SPLIT;

    const float* Arow = A + (size_t)(bm * EBM) * DIN;

    // issue one k-tile stage into buffer `buf`
    auto ISSUE = [&](int kt, int buf) {
        float* sb = smem_dyn + buf * ESTAGE_FLTS;
        const int kg = kt * EBK + lane;
        const int bytes = (kg < DIN) ? 4 : 0;
        // A: rows 8i + w, i = 0..15
#pragma unroll
        for (int i = 0; i < 16; i++) {
            const int row = 8 * i + w;
            cp_async4(sb + row * EKPAD + lane, Arow + (size_t)row * DIN + kg, bytes);
        }
        // B: rows 8i + w, i = 0..7
        float* sbB = sb + EBM * EKPAD;
#pragma unroll
        for (int i = 0; i < 8; i++) {
            const int row = 8 * i + w;
            cp_async4(sbB + row * EKPAD + lane, Bw + (size_t)row * DIN + kg, bytes);
        }
    };

    float acc[2][4][4];
#pragma unroll
    for (int a = 0; a < 2; a++)
#pragma unroll
        for (int b = 0; b < 4; b++)
#pragma unroll
            for (int c = 0; c < 4; c++) acc[a][b][c] = 0.f;

    // prologue: fill stages 0,1
    ISSUE(ktb + 0, 0); CP_COMMIT();
    ISSUE(ktb + 1, 1); CP_COMMIT();

    const int ar = lane >> 2;
    const int ac = lane & 3;

    for (int i = 0; i < KT_PER_SPLIT; i++) {
        CP_WAIT(1);
        __syncthreads();

        const int buf = i % ESTAGES;
        const float* as = smem_dyn + buf * ESTAGE_FLTS + (wm * 32) * EKPAD;
        const float* bs = smem_dyn + buf * ESTAGE_FLTS + EBM * EKPAD + (wn * 32) * EKPAD;

#pragma unroll
        for (int kk = 0; kk < 4; kk++) {
            const int k0 = kk * 8;
            unsigned a[2][4], b[4][2];
#pragma unroll
            for (int mt = 0; mt < 2; mt++) {
                const float* p = as + (mt * 16 + ar) * EKPAD + k0 + ac;
                a[mt][0] = __float_as_uint(p[0]);
                a[mt][1] = __float_as_uint(p[8 * EKPAD]);
                a[mt][2] = __float_as_uint(p[4]);
                a[mt][3] = __float_as_uint(p[8 * EKPAD + 4]);
            }
#pragma unroll
            for (int nt = 0; nt < 4; nt++) {
                const float* p = bs + (nt * 8 + ar) * EKPAD + k0 + ac;
                b[nt][0] = __float_as_uint(p[0]);
                b[nt][1] = __float_as_uint(p[4]);
            }
#pragma unroll
            for (int mt = 0; mt < 2; mt++)
#pragma unroll
                for (int nt = 0; nt < 4; nt++)
                    asm volatile(
                        "mma.sync.aligned.m16n8k8.row.col.f32.tf32.tf32.f32 "
                        "{%0,%1,%2,%3}, {%4,%5,%6,%7}, {%8,%9}, {%0,%1,%2,%3};\n"
                        : "+f"(acc[mt][nt][0]), "+f"(acc[mt][nt][1]),
                          "+f"(acc[mt][nt][2]), "+f"(acc[mt][nt][3])
                        : "r"(a[mt][0]), "r"(a[mt][1]), "r"(a[mt][2]), "r"(a[mt][3]),
                          "r"(b[nt][0]), "r"(b[nt][1]));
        }

        const int nkt = i + ESTAGES - 1;           // next stage to issue
        if (nkt < KT_PER_SPLIT) ISSUE(ktb + nkt, nkt % ESTAGES);
        CP_COMMIT();
    }

    // epilogue: atomic accumulate into pre-biased C
    const int row0 = bm * EBM + wm * 32 + (lane >> 2);
    const int col0 = wn * 32 + (lane & 3) * 2;
#pragma unroll
    for (int mt = 0; mt < 2; mt++) {
#pragma unroll
        for (int nt = 0; nt < 4; nt++) {
            const int c0 = col0 + nt * 8;
            const int r  = row0 + mt * 16;
            atomicAdd(&C[(size_t)r * EBN + c0],           acc[mt][nt][0]);
            atomicAdd(&C[(size_t)r * EBN + c0 + 1],       acc[mt][nt][1]);
            atomicAdd(&C[(size_t)(r + 8) * EBN + c0],     acc[mt][nt][2]);
            atomicAdd(&C[(size_t)(r + 8) * EBN + c0 + 1], acc[mt][nt][3]);
        }
    }
}

// bias pre-fill for the atomic epilogue
__global__ void z_init_kernel(const float* __restrict__ b_enc, float* __restrict__ z)
{
    const int idx = blockIdx.x * blockDim.x + threadIdx.x;
    if (idx < MROWS * DMODEL) z[idx] = b_enc[idx & (DMODEL - 1)];
}

// ================= generic tf32 GEMM (small GEMMs: xz, dbl) =================
#define BM 128
#define BN 64
#define BK 32
#define KPAD 36

__device__ __forceinline__ unsigned f2tf(float x) {
    unsigned r;
    asm("cvt.rna.tf32.f32 %0, %1;" : "=r"(r) : "f"(x));
    return r;
}

__global__ void __launch_bounds__(256, 1) gemm_tf32_kernel(
    const float* __restrict__ A, const float* __restrict__ Bw,
    const float* __restrict__ bias, float* __restrict__ C,
    int M, int N, int K)
{
    float* As = smem_dyn;
    float* Bs = smem_dyn + 2 * BM * KPAD;

    const int tid  = threadIdx.x;
    const int lane = tid & 31;
    const int warp = tid >> 5;
    const int wm   = warp & 3;
    const int wn   = warp >> 2;
    const int bm   = blockIdx.x;
    const int bn   = blockIdx.y;

    const int lcol = tid & 31;
    const int lrow = tid >> 5;

    float areg[16];
    float breg[8];

    const int nkt = (K + BK - 1) / BK;

    auto LOAD = [&](int kt) {
        const int k0 = kt * BK + lcol;
        const bool kin = (k0 < K);
        const float* ap = A + (size_t)(bm * BM + lrow) * K + k0;
#pragma unroll
        for (int i = 0; i < 16; i++)
            areg[i] = kin ? ap[(size_t)(i * 8) * K] : 0.f;
#pragma unroll
        for (int i = 0; i < 8; i++) {
            int gn = bn * BN + lrow + i * 8;
            breg[i] = (kin && gn < N) ? Bw[(size_t)gn * K + k0] : 0.f;
        }
    };
    auto STS = [&](int buf) {
        float* as = As + buf * BM * KPAD;
        float* bs = Bs + buf * BN * KPAD;
#pragma unroll
        for (int i = 0; i < 16; i++)
            as[(lrow + i * 8) * KPAD + lcol] = __uint_as_float(f2tf(areg[i]));
#pragma unroll
        for (int i = 0; i < 8; i++)
            bs[(lrow + i * 8) * KPAD + lcol] = __uint_as_float(f2tf(breg[i]));
    };

    float acc[2][4][4];
#pragma unroll
    for (int a = 0; a < 2; a++)
#pragma unroll
        for (int b = 0; b < 4; b++)
#pragma unroll
            for (int c = 0; c < 4; c++) acc[a][b][c] = 0.f;

    LOAD(0);
    STS(0);
    __syncthreads();

    for (int kt = 0; kt < nkt; kt++) {
        const int buf = kt & 1;
        if (kt + 1 < nkt) LOAD(kt + 1);

        const float* as = As + buf * BM * KPAD + (wm * 32) * KPAD;
        const float* bs = Bs + buf * BN * KPAD + (wn * 32) * KPAD;

        const int ar = lane >> 2;
        const int ac = lane & 3;
#pragma unroll
        for (int kk = 0; kk < 4; kk++) {
            const int k0 = kk * 8;
            unsigned a[2][4], b[4][2];
#pragma unroll
            for (int mt = 0; mt < 2; mt++) {
                const float* p = as + (mt * 16 + ar) * KPAD + k0 + ac;
                a[mt][0] = __float_as_uint(p[0]);
                a[mt][1] = __float_as_uint(p[8 * KPAD]);
                a[mt][2] = __float_as_uint(p[4]);
                a[mt][3] = __float_as_uint(p[8 * KPAD + 4]);
            }
#pragma unroll
            for (int nt = 0; nt < 4; nt++) {
                const float* p = bs + (nt * 8 + ar) * KPAD + k0 + ac;
                b[nt][0] = __float_as_uint(p[0]);
                b[nt][1] = __float_as_uint(p[4]);
            }
#pragma unroll
            for (int mt = 0; mt < 2; mt++)
#pragma unroll
                for (int nt = 0; nt < 4; nt++)
                    asm volatile(
                        "mma.sync.aligned.m16n8k8.row.col.f32.tf32.tf32.f32 "
                        "{%0,%1,%2,%3}, {%4,%5,%6,%7}, {%8,%9}, {%0,%1,%2,%3};\n"
                        : "+f"(acc[mt][nt][0]), "+f"(acc[mt][nt][1]),
                          "+f"(acc[mt][nt][2]), "+f"(acc[mt][nt][3])
                        : "r"(a[mt][0]), "r"(a[mt][1]), "r"(a[mt][2]), "r"(a[mt][3]),
                          "r"(b[nt][0]), "r"(b[nt][1]));
        }
        if (kt + 1 < nkt) STS(buf ^ 1);
        __syncthreads();
    }

    const int row0 = bm * BM + wm * 32 + (lane >> 2);
    const int col0 = bn * BN + wn * 32 + (lane & 3) * 2;
#pragma unroll
    for (int mt = 0; mt < 2; mt++) {
#pragma unroll
        for (int nt = 0; nt < 4; nt++) {
            const int c0 = col0 + nt * 8;
            const int r  = row0 + mt * 16;
            if (c0 < N) {
                const float b0v = bias ? bias[c0]     : 0.f;
                const float b1v = bias ? bias[c0 + 1] : 0.f;
                C[(size_t)r * N + c0]           = acc[mt][nt][0] + b0v;
                C[(size_t)r * N + c0 + 1]       = acc[mt][nt][1] + b1v;
                C[(size_t)(r + 8) * N + c0]     = acc[mt][nt][2] + b0v;
                C[(size_t)(r + 8) * N + c0 + 1] = acc[mt][nt][3] + b1v;
            }
        }
    }
}

// ---------------- causal depthwise conv (kernel 4) + bias + SiLU ----------------
__global__ void conv_silu_kernel(const float* __restrict__ xz,
                                 const float* __restrict__ cw,
                                 const float* __restrict__ cb,
                                 float* __restrict__ xconv)
{
    const int gid = blockIdx.x * blockDim.x + threadIdx.x;
    if (gid >= MROWS * DINNER) return;
    const int d = gid & (DINNER - 1);
    const int t = (gid >> 7) & (TT - 1);

    const float w0 = cw[d * 4 + 0], w1 = cw[d * 4 + 1];
    const float w2 = cw[d * 4 + 2], w3 = cw[d * 4 + 3];

    const float* xp = xz + (size_t)(gid >> 7) * (2 * DINNER) + d;
    float acc = cb[d] + xp[0] * w3;
    if (t >= 1) acc += xp[-(2 * DINNER)] * w2;
    if (t >= 2) acc += xp[-(4 * DINNER)] * w1;
    if (t >= 3) acc += xp[-(6 * DINNER)] * w0;

    xconv[gid] = acc / (1.f + __expf(-acc));
}

// ---------------- dt = softplus(dbl[:, :4] @ W_dt^T + b_dt) ----------------
__global__ void dt_kernel(const float* __restrict__ dbl,
                          const float* __restrict__ Wdt,
                          const float* __restrict__ bdt,
                          float* __restrict__ dtb)
{
    const int gid = blockIdx.x * blockDim.x + threadIdx.x;
    if (gid >= MROWS * DINNER) return;
    const int d   = gid & (DINNER - 1);
    const int row = gid >> 7;
    const float* xr = dbl + (size_t)row * NDBL;
    float v = bdt[d];
#pragma unroll
    for (int r = 0; r < 4; r++) v += xr[r] * Wdt[d * 4 + r];
    dtb[gid] = (v > 20.f) ? v : log1pf(__expf(v));
}

// ---------------- selective scan + gate + D-skip + T-mean ----------------
__device__ __forceinline__ float ex2(float x) {
    float r;
    asm("ex2.approx.ftz.f32 %0, %1;" : "=f"(r) : "f"(x));
    return r;
}

__global__ void __launch_bounds__(128, 1) scan_kernel(
    const float* __restrict__ dbl, const float* __restrict__ dtb,
    const float* __restrict__ xconv, const float* __restrict__ xz,
    const float* __restrict__ A_log, const float* __restrict__ D_skip,
    float* __restrict__ ybar)
{
    const int b = blockIdx.x;
    const int d = threadIdx.x;

    __shared__ float sB[8][DSTATE];
    __shared__ float sC[8][DSTATE];

    float a2[DSTATE];
#pragma unroll
    for (int n = 0; n < DSTATE; n++)
        a2[n] = -__expf(A_log[d * DSTATE + n]) * 1.4426950408889634f;

    const float dsk = D_skip[d];
    float h[DSTATE];
#pragma unroll
    for (int n = 0; n < DSTATE; n++) h[n] = 0.f;
    float ys = 0.f;

    for (int t0 = 0; t0 < TT; t0 += 8) {
        __syncthreads();
        for (int i = d; i < 8 * 32; i += 128) {
            const int tt = i >> 5, j = i & 31;
            const float v = dbl[(size_t)(b * TT + t0 + tt) * NDBL + DTRANK + j];
            if (j < DSTATE) sB[tt][j] = v;
            else            sC[tt][j - DSTATE] = v;
        }
        __syncthreads();
#pragma unroll
        for (int tt = 0; tt < 8; tt++) {
            const int row = b * TT + t0 + tt;
            const float dtv = dtb[(size_t)row * DINNER + d];
            const float xc  = xconv[(size_t)row * DINNER + d];
            const float g   = xz[(size_t)row * (2 * DINNER) + DINNER + d];
            const float s   = dtv * xc;
            float y = 0.f;
#pragma unroll
            for (int n = 0; n < DSTATE; n++) {
                const float dA = ex2(dtv * a2[n]);
                h[n] = dA * h[n] + s * sB[tt][n];
                y += h[n] * sC[tt][n];
            }
            y += dsk * xc;
            y *= g / (1.f + __expf(-g));
            ys += y;
        }
    }
    ybar[b * DINNER + d] = ys * (1.f / (float)TT);
}

// ---------------- out-proj + heads ----------------
__global__ void head_kernel(const float* __restrict__ ybar,
                            const float* __restrict__ Wout,
                            const float* __restrict__ Wfc,  const float* __restrict__ bfc,
                            const float* __restrict__ Wmu,  const float* __restrict__ bmu,
                            const float* __restrict__ Wsig, const float* __restrict__ bsig,
                            float* __restrict__ out)
{
    const int b = blockIdx.x;
    const int tid = threadIdx.x;
    __shared__ float yb[DINNER], ev[DMODEL], xv[LINDIM];

    if (tid < DINNER) yb[tid] = ybar[b * DINNER + tid];
    __syncthreads();

    if (tid < DMODEL) {
        float a = 0.f;
#pragma unroll 4
        for (int dd = 0; dd < DINNER; dd++) a += yb[dd] * Wout[tid * DINNER + dd];
        ev[tid] = a;
    }
    __syncthreads();

    if (tid < LINDIM) {
        float a = bfc[tid];
#pragma unroll 4
        for (int m = 0; m < DMODEL; m++) a += ev[m] * Wfc[tid * DMODEL + m];
        const float th = tanhf(a);
        const float x = (th > 0.f) ? th : expm1f(th);
        xv[tid] = x;
        out[b * LINDIM + tid] = x;
    }
    __syncthreads();

    {
        const int o = tid;
        float m = bmu[o], sg = bsig[o];
#pragma unroll 4
        for (int j = 0; j < LINDIM; j++) {
            const float xj = xv[j];
            m  += xj * Wmu[o * LINDIM + j];
            sg += xj * Wsig[o * LINDIM + j];
        }
        out[BB * LINDIM + b * DIMOUT + o] = m;
        const float el = (sg > 0.f) ? sg : expm1f(sg);
        out[BB * LINDIM + BB * DIMOUT + b * DIMOUT + o] = el + 1.f + 1e-14f;
    }
}

// ---------------- launch ----------------
extern "C" void kernel_launch(void* const* d_in, const int* in_sizes, int n_in,
                              void* d_out, int out_size)
{
    const float* input  = (const float*)d_in[0];
    const float* W_enc  = (const float*)d_in[1];
    const float* b_enc  = (const float*)d_in[2];
    const float* W_in   = (const float*)d_in[3];
    const float* conv_w = (const float*)d_in[4];
    const float* conv_b = (const float*)d_in[5];
    const float* W_x    = (const float*)d_in[6];
    const float* W_dt   = (const float*)d_in[7];
    const float* b_dt   = (const float*)d_in[8];
    const float* A_log  = (const float*)d_in[9];
    const float* D_skip = (const float*)d_in[10];
    const float* W_out  = (const float*)d_in[11];
    const float* W_fc   = (const float*)d_in[12];
    const float* b_fc   = (const float*)d_in[13];
    const float* W_mu   = (const float*)d_in[14];
    const float* b_mu   = (const float*)d_in[15];
    const float* W_sig  = (const float*)d_in[16];
    const float* b_sig  = (const float*)d_in[17];
    float* out = (float*)d_out;

    float *z, *xz, *xconv, *dbl, *dtb, *ybar;
    cudaGetSymbolAddress((void**)&z,     g_z);
    cudaGetSymbolAddress((void**)&xz,    g_xz);
    cudaGetSymbolAddress((void**)&xconv, g_xconv);
    cudaGetSymbolAddress((void**)&dbl,   g_dbl);
    cudaGetSymbolAddress((void**)&dtb,   g_dt);
    cudaGetSymbolAddress((void**)&ybar,  g_ybar);

    const int encSmem = ESTAGES * ESTAGE_FLTS * (int)sizeof(float);   // 82944
    cudaFuncSetAttribute(enc_gemm_kernel,
                         cudaFuncAttributeMaxDynamicSharedMemorySize, encSmem);
    const int smemBytes = (2 * BM * KPAD + 2 * BN * KPAD) * (int)sizeof(float); // 55296
    cudaFuncSetAttribute(gemm_tf32_kernel,
                         cudaFuncAttributeMaxDynamicSharedMemorySize, smemBytes);

    // 1a. z = bias
    z_init_kernel<<<(MROWS * DMODEL) / 256, 256>>>(b_enc, z);
    // 1b. z += input @ W_enc^T   (split-K x4, cp.async pipelined)
    enc_gemm_kernel<<<dim3(MROWS / EBM, 1, NSPLIT), 256, encSmem>>>(input, W_enc, z);

    // 2. xz = z @ W_in^T
    gemm_tf32_kernel<<<dim3(MROWS / BM, (2 * DINNER) / BN), 256, smemBytes>>>(
        z, W_in, nullptr, xz, MROWS, 2 * DINNER, DMODEL);

    // 3. causal conv + silu
    conv_silu_kernel<<<(MROWS * DINNER) / 256, 256>>>(xz, conv_w, conv_b, xconv);

    // 4. dbl = x_conv @ W_x^T
    gemm_tf32_kernel<<<dim3(MROWS / BM, 1), 256, smemBytes>>>(
        xconv, W_x, nullptr, dbl, MROWS, NDBL, DINNER);

    // 5. dt = softplus(dbl[:, :4] @ W_dt^T + b_dt)
    dt_kernel<<<(MROWS * DINNER) / 256, 256>>>(dbl, W_dt, b_dt, dtb);

    // 6. selective scan + gate + skip + T-mean
    scan_kernel<<<BB, DINNER>>>(dbl, dtb, xconv, xz, A_log, D_skip, ybar);

    // 7. out-proj + heads -> (x, mu, sigma)
    head_kernel<<<BB, 256>>>(ybar, W_out, W_fc, b_fc, W_mu, b_mu, W_sig, b_sig, out);
}